// round 11
// baseline (speedup 1.0000x reference)
#include <cuda_runtime.h>
#include <cuda_bf16.h>
#include <mma.h>
#include <math.h>
#include <cstdint>
using namespace nvcuda;

// ---------------- problem constants ----------------
#define B_  2
#define S_  2048
#define D_  1024
#define H_  16
#define DH_ 64
#define F_  4096
#define E_  8
#define NTOK (B_*S_)          // 4096
#define NASSIGN (NTOK*2)      // 8192

// ---------------- scratch ----------------
__device__ float g_h   [NTOK*D_];      // LN output (tf32-rounded)
__device__ float g_q   [NTOK*D_];
__device__ float g_k   [NTOK*D_];
__device__ float g_v   [NTOK*D_];
__device__ float g_attn[NTOK*D_];
__device__ float g_x1  [NTOK*D_];      // exact fp32 (residual/router)
__device__ float g_x1t [NTOK*D_];      // tf32-rounded (MoE GEMM A)
__device__ float g_h1  [(size_t)NASSIGN*F_];
__device__ float g_h2  [NASSIGN*D_];
// routing
__device__ int   g_counts[E_];
__device__ int   g_off[E_];
__device__ int   g_cur[E_];
__device__ int   g_tok[NASSIGN];
__device__ int   g_te [NASSIGN];
__device__ float g_tw [NASSIGN];
__device__ int   g_rowid[NASSIGN];

// ---------------- helpers ----------------
__device__ __forceinline__ void cp_async16(float* sdst, const float* gsrc, bool valid) {
    unsigned int sa = (unsigned int)__cvta_generic_to_shared(sdst);
    int sz = valid ? 16 : 0;
    asm volatile("cp.async.cg.shared.global [%0], [%1], 16, %2;\n"
                 :: "r"(sa), "l"(gsrc), "r"(sz));
}
__device__ __forceinline__ void cp_commit() { asm volatile("cp.async.commit_group;\n" ::); }
template<int N> __device__ __forceinline__ void cp_wait() { asm volatile("cp.async.wait_group %0;\n" :: "n"(N)); }

__device__ __forceinline__ float rtf32(float x) { return wmma::__float_to_tf32(x); }
__device__ __forceinline__ float gelu_f(float x) {
    float u = 0.7978845608028654f * (x + 0.044715f * x * x * x);
    float t = 1.f - 2.f / (__expf(2.f * u) + 1.f);
    return 0.5f * x * (1.f + t);
}

// ---------------- small kernels ----------------
__global__ void k_zero_counts() { if (threadIdx.x < E_) g_counts[threadIdx.x] = 0; }

__global__ void k_ln(const float* __restrict__ x, const float* __restrict__ g,
                     const float* __restrict__ b) {
    int row = blockIdx.x;
    const float* xr = x + (size_t)row * D_;
    float s = 0.f, s2 = 0.f;
    for (int d = threadIdx.x; d < D_; d += blockDim.x) { float v = xr[d]; s += v; s2 += v * v; }
    __shared__ float sh1[8], sh2[8];
    int lane = threadIdx.x & 31, wid = threadIdx.x >> 5;
    #pragma unroll
    for (int o = 16; o; o >>= 1) { s += __shfl_xor_sync(~0u, s, o); s2 += __shfl_xor_sync(~0u, s2, o); }
    if (lane == 0) { sh1[wid] = s; sh2[wid] = s2; }
    __syncthreads();
    if (wid == 0) {
        s  = (lane < 8) ? sh1[lane] : 0.f;
        s2 = (lane < 8) ? sh2[lane] : 0.f;
        #pragma unroll
        for (int o = 4; o; o >>= 1) { s += __shfl_xor_sync(~0u, s, o); s2 += __shfl_xor_sync(~0u, s2, o); }
        if (lane == 0) { sh1[0] = s; sh2[0] = s2; }
    }
    __syncthreads();
    float mean = sh1[0] * (1.f / D_);
    float var  = sh2[0] * (1.f / D_) - mean * mean;
    float rstd = rsqrtf(var + 1e-5f);
    for (int d = threadIdx.x; d < D_; d += blockDim.x)
        g_h[(size_t)row * D_ + d] = rtf32((xr[d] - mean) * rstd * g[d] + b[d]);
}

// ---------------- wmma tf32 GEMM — 64x64 warp tiles, 3-stage cp.async ----------------
// MODE 0: fused QKV: z selects weight {Bm,R,bias} and output {g_q,g_k,g_v}
// MODE 1: x1 = A@B + R (exact) ; x1t = tf32(x1)
// MODE 2: h1 = tf32(gelu(gather(x1t)@W1[e]+b1[e]))   [BN=256, 256 thr]
// MODE 3: h2 = h1@W2[e]+b2[e] (exact)
template<int BM, int BN, int MODE, int NTT>
__global__ __launch_bounds__(NTT, (NTT == 128 ? 2 : 1)) void k_mma(
    const float* __restrict__ A, const float* __restrict__ Bm,
    float* __restrict__ C, const float* __restrict__ R,
    const float* __restrict__ bias)
{
    constexpr int BK = 32;
    constexpr int AP = BK + 4;
    constexpr int BP = BN + 4;
    constexpr int KD  = (MODE==3) ? F_ : D_;
    constexpr int LDA = (MODE==3) ? F_ : D_;
    constexpr int LDB = (MODE==2) ? F_ : D_;
    constexpr int KT  = KD / BK;
    constexpr int ASZ = BM * AP;
    constexpr int BSZ = BK * BP;

    extern __shared__ float smx[];
    float* As = smx;                // [3][ASZ]
    float* Bs = smx + 3 * ASZ;      // [3][BSZ]
    float* stage = smx;             // aliased after final sync

    const int tid = threadIdx.x;
    const int m0 = blockIdx.y * BM;
    const int n0 = blockIdx.x * BN;

    int e = 0, base = 0, count = NTOK;
    if constexpr (MODE == 2 || MODE == 3) {
        e = blockIdx.z;
        count = g_counts[e];
        if (m0 >= count) return;
        base = g_off[e];
    }

    const float* Ap;
    const float* Bp;
    float* qkvout = nullptr;
    if constexpr (MODE == 0) {
        int z = blockIdx.z;
        Ap = A;
        Bp = (z == 0) ? Bm : (z == 1) ? R : bias;
        qkvout = (z == 0) ? g_q : (z == 1) ? g_k : g_v;
    } else if constexpr (MODE == 2) { Ap = g_x1t; Bp = Bm + (size_t)e * D_ * F_; }
    else if constexpr (MODE == 3)   { Ap = g_h1;  Bp = Bm + (size_t)e * F_ * D_; }
    else                            { Ap = A; Bp = Bm; }

    __shared__ int rowid[BM];
    for (int r = tid; r < BM; r += NTT) {
        int src;
        if constexpr (MODE == 2)      src = (m0 + r < count) ? g_tok[base + m0 + r] : -1;
        else if constexpr (MODE == 3) src = (m0 + r < count) ? (base + m0 + r) : -1;
        else                          src = m0 + r;
        rowid[r] = src;
    }
    __syncthreads();

    auto issue = [&](int kt, int bufi) {
        if (kt < KT) {
            const int k0 = kt * BK;
            float* Ad = As + bufi * ASZ;
            float* Bd = Bs + bufi * BSZ;
            constexpr int AV = BM * BK / (4 * NTT);
            #pragma unroll
            for (int i = 0; i < AV; i++) {
                int idx = tid + i * NTT;
                int r = idx >> 3, c = (idx & 7) << 2;
                int src = rowid[r];
                const float* g = Ap + (size_t)(src < 0 ? 0 : src) * LDA + k0 + c;
                cp_async16(Ad + r * AP + c, g, src >= 0);
            }
            constexpr int BV = BK * BN / (4 * NTT);
            constexpr int BG = BN / 4;
            #pragma unroll
            for (int i = 0; i < BV; i++) {
                int idx = tid + i * NTT;
                int r = idx / BG, c = (idx % BG) << 2;
                const float* g = Bp + (size_t)(k0 + r) * LDB + n0 + c;
                cp_async16(Bd + r * BP + c, g, true);
            }
        }
        cp_commit();
    };

    // warps in (BM/64) x (BN/64) grid; warp tile 64x64 (MI=NI=4)
    constexpr int MWARP = BM / 64;
    constexpr int MI = 4, NI = 4;
    const int warp = tid >> 5;
    const int wm = (warp % MWARP) * 64;
    const int wn = (warp / MWARP) * 64;

    wmma::fragment<wmma::accumulator, 16, 16, 8, float> cf[MI][NI];
    #pragma unroll
    for (int i = 0; i < MI; i++)
        #pragma unroll
        for (int j = 0; j < NI; j++) wmma::fill_fragment(cf[i][j], 0.f);

    using AF = wmma::fragment<wmma::matrix_a, 16, 16, 8, wmma::precision::tf32, wmma::row_major>;
    using BF = wmma::fragment<wmma::matrix_b, 16, 16, 8, wmma::precision::tf32, wmma::row_major>;

    issue(0, 0);
    issue(1, 1);
    issue(2, 2);
    for (int kt = 0; kt < KT; kt++) {
        const int buf = kt % 3;
        cp_wait<2>();
        __syncthreads();
        const float* Ab = As + buf * ASZ;
        const float* Bb = Bs + buf * BSZ;
        #pragma unroll
        for (int kk = 0; kk < BK / 8; kk++) {
            AF af[MI];
            #pragma unroll
            for (int i = 0; i < MI; i++)
                wmma::load_matrix_sync(af[i], Ab + (wm + i * 16) * AP + kk * 8, AP);
            BF bf[NI];
            #pragma unroll
            for (int j = 0; j < NI; j++)
                wmma::load_matrix_sync(bf[j], Bb + (kk * 8) * BP + wn + j * 16, BP);
            #pragma unroll
            for (int i = 0; i < MI; i++)
                #pragma unroll
                for (int j = 0; j < NI; j++)
                    wmma::mma_sync(cf[i][j], af[i], bf[j], cf[i][j]);
        }
        __syncthreads();
        issue(kt + 3, buf);
    }

    #pragma unroll
    for (int i = 0; i < MI; i++)
        #pragma unroll
        for (int j = 0; j < NI; j++)
            wmma::store_matrix_sync(stage + (wm + i * 16) * BP + wn + j * 16,
                                    cf[i][j], BP, wmma::mem_row_major);
    __syncthreads();

    constexpr int EV = BM * BN / NTT;
    #pragma unroll 8
    for (int i = 0; i < EV; i++) {
        int idx = tid + i * NTT;
        int m = idx / BN, n = idx % BN;
        float v = stage[m * BP + n];
        if constexpr (MODE == 0) {
            qkvout[(size_t)(m0 + m) * D_ + n0 + n] = rtf32(v);
        } else if constexpr (MODE == 1) {
            size_t o = (size_t)(m0 + m) * D_ + n0 + n;
            float val = v + R[o];
            C[o] = val;
            g_x1t[o] = rtf32(val);
        } else if constexpr (MODE == 2) {
            if (m0 + m < count)
                g_h1[(size_t)(base + m0 + m) * F_ + n0 + n] =
                    rtf32(gelu_f(v + bias[(size_t)e * F_ + n0 + n]));
        } else {
            if (m0 + m < count)
                g_h2[(size_t)(base + m0 + m) * D_ + n0 + n] = v + bias[(size_t)e * D_ + n0 + n];
        }
    }
}

// ---------------- fused flash attention — 128 threads, 4 warps, 32x64 warp tiles ----------------
#define FQ_OFF 0
#define FK_OFF 8704
#define FV_OFF 13056
#define FP_OFF 17408
#define FR_OFF 26112
#define FSM_TOTAL ((26112 + 128) * 4)

__global__ __launch_bounds__(128, 2) void k_flash() {
    extern __shared__ float sm[];
    float* Qs = sm + FQ_OFF;
    float* Ks = sm + FK_OFF;
    float* Vs = sm + FV_OFF;
    float* Ps = sm + FP_OFF;
    float* rs = sm + FR_OFF;

    const int tid = threadIdx.x, warp = tid >> 5;
    const int z = blockIdx.y, bb = z >> 4, hh = z & 15;
    const int q0 = blockIdx.x * 128;
    const float* Qg = g_q + (size_t)(bb * S_ + q0) * D_ + hh * DH_;
    const float* Kg = g_k + (size_t)(bb * S_) * D_ + hh * DH_;
    const float* Vg = g_v + (size_t)(bb * S_) * D_ + hh * DH_;

    #pragma unroll
    for (int i = 0; i < 16; i++) {
        int idx = tid + i * 128;
        int r = idx >> 4, c = (idx & 15) << 2;
        cp_async16(Qs + r * 68 + c, Qg + (size_t)r * D_ + c, true);
    }
    cp_commit();
    rs[tid] = 0.f;

    auto loadK = [&](int c) {
        if (c < S_ / 64) {
            const float* src = Kg + (size_t)(c * 64) * D_;
            #pragma unroll
            for (int i = 0; i < 8; i++) {
                int idx = tid + i * 128;
                int r = idx >> 4, cc = (idx & 15) << 2;
                cp_async16(Ks + r * 68 + cc, src + (size_t)r * D_ + cc, true);
            }
        }
        cp_commit();
    };
    auto loadV = [&](int c) {
        if (c < S_ / 64) {
            const float* src = Vg + (size_t)(c * 64) * D_;
            #pragma unroll
            for (int i = 0; i < 8; i++) {
                int idx = tid + i * 128;
                int r = idx >> 4, cc = (idx & 15) << 2;
                cp_async16(Vs + r * 68 + cc, src + (size_t)r * D_ + cc, true);
            }
        }
        cp_commit();
    };
    loadK(0);
    loadV(0);

    const int wm = warp * 32;
    using AF  = wmma::fragment<wmma::matrix_a, 16, 16, 8, wmma::precision::tf32, wmma::row_major>;
    using BFc = wmma::fragment<wmma::matrix_b, 16, 16, 8, wmma::precision::tf32, wmma::col_major>;
    using BFr = wmma::fragment<wmma::matrix_b, 16, 16, 8, wmma::precision::tf32, wmma::row_major>;

    wmma::fragment<wmma::accumulator, 16, 16, 8, float> of[2][4];
    #pragma unroll
    for (int i = 0; i < 2; i++)
        #pragma unroll
        for (int j = 0; j < 4; j++) wmma::fill_fragment(of[i][j], 0.f);

    for (int c = 0; c < S_ / 64; c++) {
        cp_wait<1>();
        __syncthreads();

        wmma::fragment<wmma::accumulator, 16, 16, 8, float> sf[2][4];
        #pragma unroll
        for (int i = 0; i < 2; i++)
            #pragma unroll
            for (int j = 0; j < 4; j++) wmma::fill_fragment(sf[i][j], 0.f);
        #pragma unroll
        for (int kk = 0; kk < DH_; kk += 8) {
            AF af[2]; BFc bf[4];
            #pragma unroll
            for (int i = 0; i < 2; i++)
                wmma::load_matrix_sync(af[i], Qs + (wm + i * 16) * 68 + kk, 68);
            #pragma unroll
            for (int j = 0; j < 4; j++)
                wmma::load_matrix_sync(bf[j], Ks + (j * 16) * 68 + kk, 68);
            #pragma unroll
            for (int i = 0; i < 2; i++)
                #pragma unroll
                for (int j = 0; j < 4; j++)
                    wmma::mma_sync(sf[i][j], af[i], bf[j], sf[i][j]);
        }
        #pragma unroll
        for (int i = 0; i < 2; i++)
            #pragma unroll
            for (int j = 0; j < 4; j++)
                wmma::store_matrix_sync(Ps + (wm + i * 16) * 68 + j * 16, sf[i][j],
                                        68, wmma::mem_row_major);
        __syncthreads();

        loadK(c + 1);

        {
            float local = 0.f;
            float* pr = Ps + tid * 68;
            #pragma unroll
            for (int j = 0; j < 64; j++) {
                float ev = __expf(0.125f * pr[j]);
                pr[j] = rtf32(ev);
                local += ev;
            }
            rs[tid] += local;
        }
        __syncthreads();

        cp_wait<1>();
        __syncthreads();

        #pragma unroll
        for (int kk = 0; kk < 64; kk += 8) {
            AF af[2]; BFr bf[4];
            #pragma unroll
            for (int i = 0; i < 2; i++)
                wmma::load_matrix_sync(af[i], Ps + (wm + i * 16) * 68 + kk, 68);
            #pragma unroll
            for (int j = 0; j < 4; j++)
                wmma::load_matrix_sync(bf[j], Vs + kk * 68 + j * 16, 68);
            #pragma unroll
            for (int i = 0; i < 2; i++)
                #pragma unroll
                for (int j = 0; j < 4; j++)
                    wmma::mma_sync(of[i][j], af[i], bf[j], of[i][j]);
        }
        __syncthreads();

        loadV(c + 1);
    }

    #pragma unroll
    for (int i = 0; i < 2; i++)
        #pragma unroll
        for (int j = 0; j < 4; j++)
            wmma::store_matrix_sync(Ps + (wm + i * 16) * 68 + j * 16, of[i][j],
                                    68, wmma::mem_row_major);
    __syncthreads();
    {
        float inv = 1.f / rs[tid];
        const float* pr = Ps + tid * 68;
        float* dst = g_attn + (size_t)(bb * S_ + q0 + tid) * D_ + hh * DH_;
        #pragma unroll
        for (int j = 0; j < 64; j++)
            dst[j] = rtf32(pr[j] * inv);
    }
}

// ---------------- router ----------------
__global__ void k_router(const float* __restrict__ Wg) {
    int w = (blockIdx.x * blockDim.x + threadIdx.x) >> 5;
    int lane = threadIdx.x & 31;
    if (w >= NTOK) return;
    const float* xr = g_x1 + (size_t)w * D_;
    float acc[E_] = {};
    for (int d = lane; d < D_; d += 32) {
        float xv = xr[d];
        const float* wr = Wg + d * E_;
        #pragma unroll
        for (int e = 0; e < E_; e++) acc[e] += xv * wr[e];
    }
    #pragma unroll
    for (int o = 16; o; o >>= 1)
        #pragma unroll
        for (int e = 0; e < E_; e++) acc[e] += __shfl_xor_sync(~0u, acc[e], o);
    if (lane == 0) {
        float l0 = -1e30f, l1 = -1e30f; int e0 = 0, e1 = 0;
        #pragma unroll
        for (int e = 0; e < E_; e++) {
            float v = acc[e];
            if (v > l0) { l1 = l0; e1 = e0; l0 = v; e0 = e; }
            else if (v > l1) { l1 = v; e1 = e; }
        }
        float w0 = 1.f / (1.f + __expf(l1 - l0));
        float w1 = 1.f - w0;
        atomicAdd(&g_counts[e0], 1);
        atomicAdd(&g_counts[e1], 1);
        g_te[2 * w] = e0;   g_te[2 * w + 1] = e1;
        g_tw[2 * w] = w0;   g_tw[2 * w + 1] = w1;
    }
}

__global__ void k_scan() {
    if (threadIdx.x == 0) {
        int off = 0;
        for (int e = 0; e < E_; e++) { g_off[e] = off; g_cur[e] = off; off += g_counts[e]; }
    }
}

__global__ void k_assign() {
    int t = blockIdx.x * blockDim.x + threadIdx.x;
    if (t >= NTOK) return;
    #pragma unroll
    for (int kk = 0; kk < 2; kk++) {
        int e = g_te[2 * t + kk];
        int row = atomicAdd(&g_cur[e], 1);
        g_tok[row] = t;
        g_rowid[2 * t + kk] = row;
    }
}

__global__ void k_final(float* __restrict__ out) {
    int t = blockIdx.x;
    int r0 = g_rowid[2 * t], r1 = g_rowid[2 * t + 1];
    float w0 = g_tw[2 * t], w1 = g_tw[2 * t + 1];
    for (int d = threadIdx.x; d < D_; d += blockDim.x) {
        out[(size_t)t * D_ + d] = g_x1[(size_t)t * D_ + d]
            + w0 * g_h2[(size_t)r0 * D_ + d]
            + w1 * g_h2[(size_t)r1 * D_ + d];
    }
}

// ---------------- launch ----------------
static constexpr int smem_tc(int BM, int BN) {
    int pipe = 3 * (BM * 36 + 32 * (BN + 4));
    int st = BM * (BN + 4);
    return 4 * (pipe > st ? pipe : st);
}

extern "C" void kernel_launch(void* const* d_in, const int* in_sizes, int n_in,
                              void* d_out, int out_size) {
    const float* x    = (const float*)d_in[0];
    const float* ln_g = (const float*)d_in[1];
    const float* ln_b = (const float*)d_in[2];
    const float* Wq   = (const float*)d_in[3];
    const float* Wk   = (const float*)d_in[4];
    const float* Wv   = (const float*)d_in[5];
    const float* Wo   = (const float*)d_in[6];
    const float* Wg   = (const float*)d_in[7];
    const float* W1   = (const float*)d_in[8];
    const float* b1   = (const float*)d_in[9];
    const float* W2   = (const float*)d_in[10];
    const float* b2   = (const float*)d_in[11];
    float* out = (float*)d_out;

    constexpr int SM_128 = smem_tc(128, 128);   // 105984
    constexpr int SM_256 = smem_tc(128, 256);   // 155136

    static bool attr_set = false;
    if (!attr_set) {
        cudaFuncSetAttribute(k_mma<128,128,0,128>, cudaFuncAttributeMaxDynamicSharedMemorySize, SM_128);
        cudaFuncSetAttribute(k_mma<128,128,1,128>, cudaFuncAttributeMaxDynamicSharedMemorySize, SM_128);
        cudaFuncSetAttribute(k_mma<128,256,2,256>, cudaFuncAttributeMaxDynamicSharedMemorySize, SM_256);
        cudaFuncSetAttribute(k_mma<128,128,3,128>, cudaFuncAttributeMaxDynamicSharedMemorySize, SM_128);
        cudaFuncSetAttribute(k_flash, cudaFuncAttributeMaxDynamicSharedMemorySize, FSM_TOTAL);
        attr_set = true;
    }

    float *hh, *hattn, *hx1;
    cudaGetSymbolAddress((void**)&hh,    g_h);
    cudaGetSymbolAddress((void**)&hattn, g_attn);
    cudaGetSymbolAddress((void**)&hx1,   g_x1);

    k_zero_counts<<<1, 32>>>();
    k_ln<<<NTOK, 256>>>(x, ln_g, ln_b);

    dim3 gQKV(D_ / 128, NTOK / 128, 3);   // (8, 32, 3)
    k_mma<128,128,0,128><<<gQKV, 128, SM_128>>>(hh, Wq, nullptr, Wk, Wv);

    dim3 gF(S_ / 128, B_ * H_);           // (16, 32)
    k_flash<<<gF, 128, FSM_TOTAL>>>();

    dim3 gP(D_ / 128, NTOK / 128);        // (8, 32)
    k_mma<128,128,1,128><<<gP, 128, SM_128>>>(hattn, Wo, hx1, x, nullptr);

    k_router<<<NTOK / 8, 256>>>(Wg);
    k_scan<<<1, 32>>>();
    k_assign<<<NTOK / 256, 256>>>();

    dim3 gU(F_ / 256, NASSIGN / 128, E_);   // (16, 64, 8) early-exit
    k_mma<128,256,2,256><<<gU, 256, SM_256>>>(nullptr, W1, nullptr, nullptr, b1);
    dim3 gD(D_ / 128, NASSIGN / 128, E_);   // (8, 64, 8)
    k_mma<128,128,3,128><<<gD, 128, SM_128>>>(nullptr, W2, nullptr, nullptr, b2);

    k_final<<<NTOK, 256>>>(out);
}

// round 13
// speedup vs baseline: 1.0084x; 1.0084x over previous
#include <cuda_runtime.h>
#include <cuda_bf16.h>
#include <mma.h>
#include <math.h>
#include <cstdint>
using namespace nvcuda;

// ---------------- problem constants ----------------
#define B_  2
#define S_  2048
#define D_  1024
#define H_  16
#define DH_ 64
#define F_  4096
#define E_  8
#define NTOK (B_*S_)          // 4096
#define NASSIGN (NTOK*2)      // 8192

// ---------------- scratch ----------------
__device__ float g_h   [NTOK*D_];      // LN output (tf32-rounded)
__device__ float g_q   [NTOK*D_];
__device__ float g_k   [NTOK*D_];
__device__ float g_v   [NTOK*D_];
__device__ float g_attn[NTOK*D_];
__device__ float g_x1  [NTOK*D_];      // exact fp32 (residual/router)
__device__ float g_x1t [NTOK*D_];      // tf32-rounded (MoE GEMM A)
__device__ float g_h1  [(size_t)NASSIGN*F_];
__device__ float g_h2  [NASSIGN*D_];
// routing
__device__ int   g_counts[E_];
__device__ int   g_off[E_];
__device__ int   g_cur[E_];
__device__ int   g_tok[NASSIGN];
__device__ int   g_te [NASSIGN];
__device__ float g_tw [NASSIGN];
__device__ int   g_rowid[NASSIGN];

// ---------------- helpers ----------------
__device__ __forceinline__ void cp_async16(float* sdst, const float* gsrc, bool valid) {
    unsigned int sa = (unsigned int)__cvta_generic_to_shared(sdst);
    int sz = valid ? 16 : 0;
    asm volatile("cp.async.cg.shared.global [%0], [%1], 16, %2;\n"
                 :: "r"(sa), "l"(gsrc), "r"(sz));
}
__device__ __forceinline__ void cp_commit() { asm volatile("cp.async.commit_group;\n" ::); }
template<int N> __device__ __forceinline__ void cp_wait() { asm volatile("cp.async.wait_group %0;\n" :: "n"(N)); }

__device__ __forceinline__ float rtf32(float x) { return wmma::__float_to_tf32(x); }
__device__ __forceinline__ float gelu_f(float x) {
    float u = 0.7978845608028654f * (x + 0.044715f * x * x * x);
    float t = 1.f - 2.f / (__expf(2.f * u) + 1.f);
    return 0.5f * x * (1.f + t);
}

// ---------------- small kernels ----------------
__global__ void k_zero_counts() { if (threadIdx.x < E_) g_counts[threadIdx.x] = 0; }

__global__ void k_ln(const float* __restrict__ x, const float* __restrict__ g,
                     const float* __restrict__ b) {
    int row = blockIdx.x;
    const float* xr = x + (size_t)row * D_;
    float s = 0.f, s2 = 0.f;
    for (int d = threadIdx.x; d < D_; d += blockDim.x) { float v = xr[d]; s += v; s2 += v * v; }
    __shared__ float sh1[8], sh2[8];
    int lane = threadIdx.x & 31, wid = threadIdx.x >> 5;
    #pragma unroll
    for (int o = 16; o; o >>= 1) { s += __shfl_xor_sync(~0u, s, o); s2 += __shfl_xor_sync(~0u, s2, o); }
    if (lane == 0) { sh1[wid] = s; sh2[wid] = s2; }
    __syncthreads();
    if (wid == 0) {
        s  = (lane < 8) ? sh1[lane] : 0.f;
        s2 = (lane < 8) ? sh2[lane] : 0.f;
        #pragma unroll
        for (int o = 4; o; o >>= 1) { s += __shfl_xor_sync(~0u, s, o); s2 += __shfl_xor_sync(~0u, s2, o); }
        if (lane == 0) { sh1[0] = s; sh2[0] = s2; }
    }
    __syncthreads();
    float mean = sh1[0] * (1.f / D_);
    float var  = sh2[0] * (1.f / D_) - mean * mean;
    float rstd = rsqrtf(var + 1e-5f);
    for (int d = threadIdx.x; d < D_; d += blockDim.x)
        g_h[(size_t)row * D_ + d] = rtf32((xr[d] - mean) * rstd * g[d] + b[d]);
}

// ---------------- wmma tf32 GEMM — 128 thr, 4 warps, 64x64 warp tiles ----------------
// 3-stage cp.async, ONE __syncthreads per K-iteration:
//   issue(kt+2) writes buffer (kt+2)%3 whose last readers (iteration kt-1)
//   are already past this iteration's top-of-loop sync.
// MODE 0: fused QKV: z selects weight {Bm,R,bias} and output {g_q,g_k,g_v}
// MODE 1: x1 = A@B + R (exact) ; x1t = tf32(x1)
// MODE 2: h1 = tf32(gelu(gather(x1t)@W1[e]+b1[e]))
// MODE 3: h2 = h1@W2[e]+b2[e] (exact)
#define NT 128

template<int BM, int BN, int MODE>
__global__ __launch_bounds__(NT, 2) void k_mma(
    const float* __restrict__ A, const float* __restrict__ Bm,
    float* __restrict__ C, const float* __restrict__ R,
    const float* __restrict__ bias)
{
    constexpr int BK = 32;
    constexpr int AP = BK + 4;
    constexpr int BP = BN + 4;
    constexpr int KD  = (MODE==3) ? F_ : D_;
    constexpr int LDA = (MODE==3) ? F_ : D_;
    constexpr int LDB = (MODE==2) ? F_ : D_;
    constexpr int KT  = KD / BK;
    constexpr int ASZ = BM * AP;
    constexpr int BSZ = BK * BP;

    extern __shared__ float smx[];
    float* As = smx;                // [3][ASZ]
    float* Bs = smx + 3 * ASZ;      // [3][BSZ]
    float* stage = smx;             // aliased after final sync

    const int tid = threadIdx.x;
    const int m0 = blockIdx.y * BM;
    const int n0 = blockIdx.x * BN;

    int e = 0, base = 0, count = NTOK;
    if constexpr (MODE == 2 || MODE == 3) {
        e = blockIdx.z;
        count = g_counts[e];
        if (m0 >= count) return;
        base = g_off[e];
    }

    const float* Ap;
    const float* Bp;
    float* qkvout = nullptr;
    if constexpr (MODE == 0) {
        int z = blockIdx.z;
        Ap = A;
        Bp = (z == 0) ? Bm : (z == 1) ? R : bias;
        qkvout = (z == 0) ? g_q : (z == 1) ? g_k : g_v;
    } else if constexpr (MODE == 2) { Ap = g_x1t; Bp = Bm + (size_t)e * D_ * F_; }
    else if constexpr (MODE == 3)   { Ap = g_h1;  Bp = Bm + (size_t)e * F_ * D_; }
    else                            { Ap = A; Bp = Bm; }

    __shared__ int rowid[BM];
    for (int r = tid; r < BM; r += NT) {
        int src;
        if constexpr (MODE == 2)      src = (m0 + r < count) ? g_tok[base + m0 + r] : -1;
        else if constexpr (MODE == 3) src = (m0 + r < count) ? (base + m0 + r) : -1;
        else                          src = m0 + r;
        rowid[r] = src;
    }
    __syncthreads();

    auto issue = [&](int kt, int bufi) {
        if (kt < KT) {
            const int k0 = kt * BK;
            float* Ad = As + bufi * ASZ;
            float* Bd = Bs + bufi * BSZ;
            constexpr int AV = BM * BK / (4 * NT);   // 8
            #pragma unroll
            for (int i = 0; i < AV; i++) {
                int idx = tid + i * NT;
                int r = idx >> 3, c = (idx & 7) << 2;
                int src = rowid[r];
                const float* g = Ap + (size_t)(src < 0 ? 0 : src) * LDA + k0 + c;
                cp_async16(Ad + r * AP + c, g, src >= 0);
            }
            constexpr int BV = BK * BN / (4 * NT);   // 8
            constexpr int BG = BN / 4;
            #pragma unroll
            for (int i = 0; i < BV; i++) {
                int idx = tid + i * NT;
                int r = idx / BG, c = (idx % BG) << 2;
                const float* g = Bp + (size_t)(k0 + r) * LDB + n0 + c;
                cp_async16(Bd + r * BP + c, g, true);
            }
        }
        cp_commit();
    };

    // 4 warps in 2x2 grid; warp tile 64x64 (MI=NI=4)
    constexpr int MI = 4, NI = 4;
    const int warp = tid >> 5;
    const int wm = (warp & 1) * 64;
    const int wn = (warp >> 1) * 64;

    wmma::fragment<wmma::accumulator, 16, 16, 8, float> cf[MI][NI];
    #pragma unroll
    for (int i = 0; i < MI; i++)
        #pragma unroll
        for (int j = 0; j < NI; j++) wmma::fill_fragment(cf[i][j], 0.f);

    using AF = wmma::fragment<wmma::matrix_a, 16, 16, 8, wmma::precision::tf32, wmma::row_major>;
    using BF = wmma::fragment<wmma::matrix_b, 16, 16, 8, wmma::precision::tf32, wmma::row_major>;

    issue(0, 0);
    issue(1, 1);
    for (int kt = 0; kt < KT; kt++) {
        const int buf = kt % 3;
        cp_wait<1>();
        __syncthreads();                 // group kt landed + all warps past prior compute
        const float* Ab = As + buf * ASZ;
        const float* Bb = Bs + buf * BSZ;
        #pragma unroll
        for (int kk = 0; kk < BK / 8; kk++) {
            AF af[MI];
            #pragma unroll
            for (int i = 0; i < MI; i++)
                wmma::load_matrix_sync(af[i], Ab + (wm + i * 16) * AP + kk * 8, AP);
            BF bf[NI];
            #pragma unroll
            for (int j = 0; j < NI; j++)
                wmma::load_matrix_sync(bf[j], Bb + (kk * 8) * BP + wn + j * 16, BP);
            #pragma unroll
            for (int i = 0; i < MI; i++)
                #pragma unroll
                for (int j = 0; j < NI; j++)
                    wmma::mma_sync(cf[i][j], af[i], bf[j], cf[i][j]);
        }
        issue(kt + 2, (kt + 2) % 3);     // writes buffer read at kt-1; safe past this sync
    }

    __syncthreads();                     // drain before smem realias
    #pragma unroll
    for (int i = 0; i < MI; i++)
        #pragma unroll
        for (int j = 0; j < NI; j++)
            wmma::store_matrix_sync(stage + (wm + i * 16) * BP + wn + j * 16,
                                    cf[i][j], BP, wmma::mem_row_major);
    __syncthreads();

    constexpr int EV = BM * BN / NT;   // 128
    #pragma unroll 8
    for (int i = 0; i < EV; i++) {
        int idx = tid + i * NT;
        int m = idx / BN, n = idx % BN;
        float v = stage[m * BP + n];
        if constexpr (MODE == 0) {
            qkvout[(size_t)(m0 + m) * D_ + n0 + n] = rtf32(v);
        } else if constexpr (MODE == 1) {
            size_t o = (size_t)(m0 + m) * D_ + n0 + n;
            float val = v + R[o];
            C[o] = val;
            g_x1t[o] = rtf32(val);
        } else if constexpr (MODE == 2) {
            if (m0 + m < count)
                g_h1[(size_t)(base + m0 + m) * F_ + n0 + n] =
                    rtf32(gelu_f(v + bias[(size_t)e * F_ + n0 + n]));
        } else {
            if (m0 + m < count)
                g_h2[(size_t)(base + m0 + m) * D_ + n0 + n] = v + bias[(size_t)e * D_ + n0 + n];
        }
    }
}

// ---------------- fused flash attention — 128 threads, 4 warps, 32x64 warp tiles ----------------
#define FQ_OFF 0
#define FK_OFF 8704
#define FV_OFF 13056
#define FP_OFF 17408
#define FR_OFF 26112
#define FSM_TOTAL ((26112 + 128) * 4)

__global__ __launch_bounds__(128, 2) void k_flash() {
    extern __shared__ float sm[];
    float* Qs = sm + FQ_OFF;
    float* Ks = sm + FK_OFF;
    float* Vs = sm + FV_OFF;
    float* Ps = sm + FP_OFF;
    float* rs = sm + FR_OFF;

    const int tid = threadIdx.x, warp = tid >> 5;
    const int z = blockIdx.y, bb = z >> 4, hh = z & 15;
    const int q0 = blockIdx.x * 128;
    const float* Qg = g_q + (size_t)(bb * S_ + q0) * D_ + hh * DH_;
    const float* Kg = g_k + (size_t)(bb * S_) * D_ + hh * DH_;
    const float* Vg = g_v + (size_t)(bb * S_) * D_ + hh * DH_;

    #pragma unroll
    for (int i = 0; i < 16; i++) {
        int idx = tid + i * 128;
        int r = idx >> 4, c = (idx & 15) << 2;
        cp_async16(Qs + r * 68 + c, Qg + (size_t)r * D_ + c, true);
    }
    cp_commit();
    rs[tid] = 0.f;

    auto loadK = [&](int c) {
        if (c < S_ / 64) {
            const float* src = Kg + (size_t)(c * 64) * D_;
            #pragma unroll
            for (int i = 0; i < 8; i++) {
                int idx = tid + i * 128;
                int r = idx >> 4, cc = (idx & 15) << 2;
                cp_async16(Ks + r * 68 + cc, src + (size_t)r * D_ + cc, true);
            }
        }
        cp_commit();
    };
    auto loadV = [&](int c) {
        if (c < S_ / 64) {
            const float* src = Vg + (size_t)(c * 64) * D_;
            #pragma unroll
            for (int i = 0; i < 8; i++) {
                int idx = tid + i * 128;
                int r = idx >> 4, cc = (idx & 15) << 2;
                cp_async16(Vs + r * 68 + cc, src + (size_t)r * D_ + cc, true);
            }
        }
        cp_commit();
    };
    loadK(0);
    loadV(0);

    const int wm = warp * 32;
    using AF  = wmma::fragment<wmma::matrix_a, 16, 16, 8, wmma::precision::tf32, wmma::row_major>;
    using BFc = wmma::fragment<wmma::matrix_b, 16, 16, 8, wmma::precision::tf32, wmma::col_major>;
    using BFr = wmma::fragment<wmma::matrix_b, 16, 16, 8, wmma::precision::tf32, wmma::row_major>;

    wmma::fragment<wmma::accumulator, 16, 16, 8, float> of[2][4];
    #pragma unroll
    for (int i = 0; i < 2; i++)
        #pragma unroll
        for (int j = 0; j < 4; j++) wmma::fill_fragment(of[i][j], 0.f);

    for (int c = 0; c < S_ / 64; c++) {
        cp_wait<1>();
        __syncthreads();

        wmma::fragment<wmma::accumulator, 16, 16, 8, float> sf[2][4];
        #pragma unroll
        for (int i = 0; i < 2; i++)
            #pragma unroll
            for (int j = 0; j < 4; j++) wmma::fill_fragment(sf[i][j], 0.f);
        #pragma unroll
        for (int kk = 0; kk < DH_; kk += 8) {
            AF af[2]; BFc bf[4];
            #pragma unroll
            for (int i = 0; i < 2; i++)
                wmma::load_matrix_sync(af[i], Qs + (wm + i * 16) * 68 + kk, 68);
            #pragma unroll
            for (int j = 0; j < 4; j++)
                wmma::load_matrix_sync(bf[j], Ks + (j * 16) * 68 + kk, 68);
            #pragma unroll
            for (int i = 0; i < 2; i++)
                #pragma unroll
                for (int j = 0; j < 4; j++)
                    wmma::mma_sync(sf[i][j], af[i], bf[j], sf[i][j]);
        }
        #pragma unroll
        for (int i = 0; i < 2; i++)
            #pragma unroll
            for (int j = 0; j < 4; j++)
                wmma::store_matrix_sync(Ps + (wm + i * 16) * 68 + j * 16, sf[i][j],
                                        68, wmma::mem_row_major);
        __syncthreads();

        loadK(c + 1);

        {
            float local = 0.f;
            float* pr = Ps + tid * 68;
            #pragma unroll
            for (int j = 0; j < 64; j++) {
                float ev = __expf(0.125f * pr[j]);
                pr[j] = rtf32(ev);
                local += ev;
            }
            rs[tid] += local;
        }
        __syncthreads();

        cp_wait<1>();
        __syncthreads();

        #pragma unroll
        for (int kk = 0; kk < 64; kk += 8) {
            AF af[2]; BFr bf[4];
            #pragma unroll
            for (int i = 0; i < 2; i++)
                wmma::load_matrix_sync(af[i], Ps + (wm + i * 16) * 68 + kk, 68);
            #pragma unroll
            for (int j = 0; j < 4; j++)
                wmma::load_matrix_sync(bf[j], Vs + kk * 68 + j * 16, 68);
            #pragma unroll
            for (int i = 0; i < 2; i++)
                #pragma unroll
                for (int j = 0; j < 4; j++)
                    wmma::mma_sync(of[i][j], af[i], bf[j], of[i][j]);
        }
        __syncthreads();

        loadV(c + 1);
    }

    #pragma unroll
    for (int i = 0; i < 2; i++)
        #pragma unroll
        for (int j = 0; j < 4; j++)
            wmma::store_matrix_sync(Ps + (wm + i * 16) * 68 + j * 16, of[i][j],
                                    68, wmma::mem_row_major);
    __syncthreads();
    {
        float inv = 1.f / rs[tid];
        const float* pr = Ps + tid * 68;
        float* dst = g_attn + (size_t)(bb * S_ + q0 + tid) * D_ + hh * DH_;
        #pragma unroll
        for (int j = 0; j < 64; j++)
            dst[j] = rtf32(pr[j] * inv);
    }
}

// ---------------- router ----------------
__global__ void k_router(const float* __restrict__ Wg) {
    int w = (blockIdx.x * blockDim.x + threadIdx.x) >> 5;
    int lane = threadIdx.x & 31;
    if (w >= NTOK) return;
    const float* xr = g_x1 + (size_t)w * D_;
    float acc[E_] = {};
    for (int d = lane; d < D_; d += 32) {
        float xv = xr[d];
        const float* wr = Wg + d * E_;
        #pragma unroll
        for (int e = 0; e < E_; e++) acc[e] += xv * wr[e];
    }
    #pragma unroll
    for (int o = 16; o; o >>= 1)
        #pragma unroll
        for (int e = 0; e < E_; e++) acc[e] += __shfl_xor_sync(~0u, acc[e], o);
    if (lane == 0) {
        float l0 = -1e30f, l1 = -1e30f; int e0 = 0, e1 = 0;
        #pragma unroll
        for (int e = 0; e < E_; e++) {
            float v = acc[e];
            if (v > l0) { l1 = l0; e1 = e0; l0 = v; e0 = e; }
            else if (v > l1) { l1 = v; e1 = e; }
        }
        float w0 = 1.f / (1.f + __expf(l1 - l0));
        float w1 = 1.f - w0;
        atomicAdd(&g_counts[e0], 1);
        atomicAdd(&g_counts[e1], 1);
        g_te[2 * w] = e0;   g_te[2 * w + 1] = e1;
        g_tw[2 * w] = w0;   g_tw[2 * w + 1] = w1;
    }
}

__global__ void k_scan() {
    if (threadIdx.x == 0) {
        int off = 0;
        for (int e = 0; e < E_; e++) { g_off[e] = off; g_cur[e] = off; off += g_counts[e]; }
    }
}

__global__ void k_assign() {
    int t = blockIdx.x * blockDim.x + threadIdx.x;
    if (t >= NTOK) return;
    #pragma unroll
    for (int kk = 0; kk < 2; kk++) {
        int e = g_te[2 * t + kk];
        int row = atomicAdd(&g_cur[e], 1);
        g_tok[row] = t;
        g_rowid[2 * t + kk] = row;
    }
}

__global__ void k_final(float* __restrict__ out) {
    int t = blockIdx.x;
    int r0 = g_rowid[2 * t], r1 = g_rowid[2 * t + 1];
    float w0 = g_tw[2 * t], w1 = g_tw[2 * t + 1];
    for (int d = threadIdx.x; d < D_; d += blockDim.x) {
        out[(size_t)t * D_ + d] = g_x1[(size_t)t * D_ + d]
            + w0 * g_h2[(size_t)r0 * D_ + d]
            + w1 * g_h2[(size_t)r1 * D_ + d];
    }
}

// ---------------- launch ----------------
static constexpr int smem_main() {
    int pipe = 3 * (128 * 36 + 32 * 132);   // 3-stage
    int st = 128 * 132;
    return 4 * (pipe > st ? pipe : st);     // 105984
}

extern "C" void kernel_launch(void* const* d_in, const int* in_sizes, int n_in,
                              void* d_out, int out_size) {
    const float* x    = (const float*)d_in[0];
    const float* ln_g = (const float*)d_in[1];
    const float* ln_b = (const float*)d_in[2];
    const float* Wq   = (const float*)d_in[3];
    const float* Wk   = (const float*)d_in[4];
    const float* Wv   = (const float*)d_in[5];
    const float* Wo   = (const float*)d_in[6];
    const float* Wg   = (const float*)d_in[7];
    const float* W1   = (const float*)d_in[8];
    const float* b1   = (const float*)d_in[9];
    const float* W2   = (const float*)d_in[10];
    const float* b2   = (const float*)d_in[11];
    float* out = (float*)d_out;

    constexpr int SM_MAIN = smem_main();

    static bool attr_set = false;
    if (!attr_set) {
        cudaFuncSetAttribute(k_mma<128,128,0>, cudaFuncAttributeMaxDynamicSharedMemorySize, SM_MAIN);
        cudaFuncSetAttribute(k_mma<128,128,1>, cudaFuncAttributeMaxDynamicSharedMemorySize, SM_MAIN);
        cudaFuncSetAttribute(k_mma<128,128,2>, cudaFuncAttributeMaxDynamicSharedMemorySize, SM_MAIN);
        cudaFuncSetAttribute(k_mma<128,128,3>, cudaFuncAttributeMaxDynamicSharedMemorySize, SM_MAIN);
        cudaFuncSetAttribute(k_flash, cudaFuncAttributeMaxDynamicSharedMemorySize, FSM_TOTAL);
        attr_set = true;
    }

    float *hh, *hattn, *hx1;
    cudaGetSymbolAddress((void**)&hh,    g_h);
    cudaGetSymbolAddress((void**)&hattn, g_attn);
    cudaGetSymbolAddress((void**)&hx1,   g_x1);

    k_zero_counts<<<1, 32>>>();
    k_ln<<<NTOK, 256>>>(x, ln_g, ln_b);

    dim3 gQKV(D_ / 128, NTOK / 128, 3);   // (8, 32, 3)
    k_mma<128,128,0><<<gQKV, NT, SM_MAIN>>>(hh, Wq, nullptr, Wk, Wv);

    dim3 gF(S_ / 128, B_ * H_);           // (16, 32)
    k_flash<<<gF, 128, FSM_TOTAL>>>();

    dim3 gP(D_ / 128, NTOK / 128);        // (8, 32)
    k_mma<128,128,1><<<gP, NT, SM_MAIN>>>(hattn, Wo, hx1, x, nullptr);

    k_router<<<NTOK / 8, 256>>>(Wg);
    k_scan<<<1, 32>>>();
    k_assign<<<NTOK / 256, 256>>>();

    dim3 gU(F_ / 128, NASSIGN / 128, E_);   // (32, 64, 8) early-exit
    k_mma<128,128,2><<<gU, NT, SM_MAIN>>>(nullptr, W1, nullptr, nullptr, b1);
    dim3 gD(D_ / 128, NASSIGN / 128, E_);   // (8, 64, 8)
    k_mma<128,128,3><<<gD, NT, SM_MAIN>>>(nullptr, W2, nullptr, nullptr, b2);

    k_final<<<NTOK, 256>>>(out);
}